// round 14
// baseline (speedup 1.0000x reference)
#include <cuda_runtime.h>
#include <cuda_bf16.h>
#include <cstdint>

#define S 2048
#define C 4096
#define K 4
#define ND 9            // offsets d=-4..4
#define KKB 36          // K*ND per precision part
#define TM 128          // samples per CTA
#define TN 64           // channels per CTA
#define NKS 7           // k-steps of 16 (K=112 >= 108)
#define QSTR 60         // b32 (k-pair) words per row
#define SMEM_BYTES ((TM + TN) * QSTR * 4)   // 46080

// Packed operands: A'[s] and B'[c] rows of 60 b32 words (120 bf16):
// layout [hi(36) | lo(36) | hi(36) | pad] along K; A'=[Ahi|Ahi|Alo], B'=[Bhi;Blo;Bhi].
__device__ uint32_t g_Apack[S * QSTR];
__device__ uint32_t g_Bpack[C * QSTR];

__global__ void prepA(const float* __restrict__ contrib, const float* __restrict__ shift) {
    const int s = blockIdx.x * blockDim.x + threadIdx.x;
    if (s >= S) return;
    float4* row4 = reinterpret_cast<float4*>(g_Apack + s * QSTR);
#pragma unroll
    for (int i = 0; i < QSTR / 4; i++) row4[i] = make_float4(0.f, 0.f, 0.f, 0.f);
    __nv_bfloat16* Ah = reinterpret_cast<__nv_bfloat16*>(g_Apack + s * QSTR);
    const float4 sh4 = __ldg(reinterpret_cast<const float4*>(shift + s * K));
    const float4 w4  = __ldg(reinterpret_cast<const float4*>(contrib + s * K));
    const float shs[4] = {sh4.x, sh4.y, sh4.z, sh4.w};
    const float ws[4]  = {w4.x,  w4.y,  w4.z,  w4.w};
#pragma unroll
    for (int k = 0; k < K; k++) {
        const float m = floorf(shs[k]);
        const float f = shs[k] - m;
        int r = (int)m + 4;                    // shift in [-4,4) -> r in [0,7]
        r = max(0, min(7, r));
        const float w1 = ws[k] * f;
        const float w0 = ws[k] - w1;
        const __nv_bfloat16 w0h = __float2bfloat16(w0);
        const __nv_bfloat16 w1h = __float2bfloat16(w1);
        const __nv_bfloat16 w0l = __float2bfloat16(w0 - __bfloat162float(w0h));
        const __nv_bfloat16 w1l = __float2bfloat16(w1 - __bfloat162float(w1h));
        const int c0 = k * ND + r;
        Ah[c0]           = w0h;  Ah[c0 + 1]           = w1h;
        Ah[c0 + KKB]     = w0h;  Ah[c0 + KKB + 1]     = w1h;
        Ah[c0 + 2 * KKB] = w0l;  Ah[c0 + 2 * KKB + 1] = w1l;
    }
}

__global__ void prepB(const float* __restrict__ comp) {
    const int c = blockIdx.x * blockDim.x + threadIdx.x;
    if (c >= C) return;
    float4* row4 = reinterpret_cast<float4*>(g_Bpack + c * QSTR);
#pragma unroll
    for (int i = 0; i < QSTR / 4; i++) row4[i] = make_float4(0.f, 0.f, 0.f, 0.f);
    __nv_bfloat16* Bh = reinterpret_cast<__nv_bfloat16*>(g_Bpack + c * QSTR);
#pragma unroll
    for (int k = 0; k < K; k++) {
#pragma unroll
        for (int d = -4; d <= 4; d++) {
            const int gc = c + d;
            const float v = (gc >= 0 && gc < C) ? __ldg(&comp[k * C + gc]) : 0.f;
            const __nv_bfloat16 vh = __float2bfloat16(v);
            const __nv_bfloat16 vl = __float2bfloat16(v - __bfloat162float(vh));
            const int kk = k * ND + d + 4;
            Bh[kk]           = vh;
            Bh[kk + KKB]     = vl;
            Bh[kk + 2 * KKB] = vh;
        }
    }
}

static __device__ __forceinline__ void mma16816(float c[4], const uint32_t a[4],
                                                uint32_t b0, uint32_t b1) {
    asm volatile(
        "mma.sync.aligned.m16n8k16.row.col.f32.bf16.bf16.f32 "
        "{%0,%1,%2,%3}, {%4,%5,%6,%7}, {%8,%9}, {%0,%1,%2,%3};"
        : "+f"(c[0]), "+f"(c[1]), "+f"(c[2]), "+f"(c[3])
        : "r"(a[0]), "r"(a[1]), "r"(a[2]), "r"(a[3]), "r"(b0), "r"(b1));
}

// Main GEMM: tile M=128 x N=64; warps 4(M) x 2(N), warp tile 32x32.
__global__ void __launch_bounds__(256, 3)
smf_hmma(float* __restrict__ out)             // (S, C)
{
    extern __shared__ uint32_t sm[];
    uint32_t* sA = sm;                 // [TM][QSTR]
    uint32_t* sB = sm + TM * QSTR;     // [TN][QSTR]

    const int tid   = threadIdx.x;
    const int wid   = tid >> 5;
    const int lane  = tid & 31;
    const int g     = lane >> 2;
    const int tg    = lane & 3;
    const int cN0   = blockIdx.x * TN;
    const int s0    = blockIdx.y * TM;
    const int warpM = wid & 3;         // 4 warps along M
    const int warpN = wid >> 2;        // 2 warps along N

    // ---- copy packed tiles (dense, full MLP) ----
    {
        const float4* srcA = reinterpret_cast<const float4*>(g_Apack + s0 * QSTR);
        float4*       dstA = reinterpret_cast<float4*>(sA);
#pragma unroll
        for (int i = 0; i < 8; i++) {                 // 1920 float4s
            const int idx = tid + 256 * i;
            if (i < 7 || idx < TM * QSTR / 4) dstA[idx] = srcA[idx];
        }
        const float4* srcB = reinterpret_cast<const float4*>(g_Bpack + cN0 * QSTR);
        float4*       dstB = reinterpret_cast<float4*>(sB);
#pragma unroll
        for (int i = 0; i < 4; i++) {                 // 960 float4s
            const int idx = tid + 256 * i;
            if (i < 3 || idx < TN * QSTR / 4) dstB[idx] = srcB[idx];
        }
    }
    __syncthreads();

    // ---- mainloop: 7 ksteps, warp tile 32(M) x 32(N) ----
    float c[2][4][4];
#pragma unroll
    for (int mi = 0; mi < 2; mi++)
#pragma unroll
        for (int nj = 0; nj < 4; nj++)
#pragma unroll
            for (int q = 0; q < 4; q++) c[mi][nj][q] = 0.f;

    const uint32_t* Abase = sA + (warpM * 32 + g) * QSTR + tg;
    const uint32_t* Bbase = sB + (warpN * 32 + g) * QSTR + tg;

#pragma unroll
    for (int ks = 0; ks < NKS; ks++) {
        uint32_t a[2][4];
#pragma unroll
        for (int mi = 0; mi < 2; mi++) {
            const uint32_t* ap = Abase + mi * 16 * QSTR + ks * 8;
            a[mi][0] = ap[0];
            a[mi][1] = ap[8 * QSTR];
            a[mi][2] = ap[4];
            a[mi][3] = ap[8 * QSTR + 4];
        }
#pragma unroll
        for (int nj = 0; nj < 4; nj++) {
            const uint32_t* bp = Bbase + nj * 8 * QSTR + ks * 8;
            const uint32_t b0 = bp[0];
            const uint32_t b1 = bp[4];
#pragma unroll
            for (int mi = 0; mi < 2; mi++)
                mma16816(c[mi][nj], a[mi], b0, b1);
        }
    }

    // ---- epilogue ----
    {
        const int row0 = s0 + warpM * 32 + g;
        const int col0 = cN0 + warpN * 32 + 2 * tg;
#pragma unroll
        for (int mi = 0; mi < 2; mi++) {
            const int r0 = row0 + 16 * mi;
#pragma unroll
            for (int nj = 0; nj < 4; nj++) {
                const int cc = col0 + 8 * nj;
                *reinterpret_cast<float2*>(out + (size_t)r0 * C + cc) =
                    make_float2(c[mi][nj][0], c[mi][nj][1]);
                *reinterpret_cast<float2*>(out + (size_t)(r0 + 8) * C + cc) =
                    make_float2(c[mi][nj][2], c[mi][nj][3]);
            }
        }
    }
}

extern "C" void kernel_launch(void* const* d_in, const int* in_sizes, int n_in,
                              void* d_out, int out_size) {
    // metadata order: inputs (unused), components, contributions, shift
    const float* comp    = (const float*)d_in[1];
    const float* contrib = (const float*)d_in[2];
    const float* shift   = (const float*)d_in[3];
    float*       out     = (float*)d_out;

    static bool configured = false;
    if (!configured) {
        cudaFuncSetAttribute(smf_hmma,
                             cudaFuncAttributeMaxDynamicSharedMemorySize, SMEM_BYTES);
        configured = true;
    }

    prepA<<<(S + 255) / 256, 256>>>(contrib, shift);
    prepB<<<(C + 255) / 256, 256>>>(comp);

    dim3 grid(C / TN, S / TM);   // (64, 16) = 1024 CTAs
    smf_hmma<<<grid, 256, SMEM_BYTES>>>(out);
}

// round 15
// speedup vs baseline: 2.5146x; 2.5146x over previous
#include <cuda_runtime.h>
#include <cuda_bf16.h>
#include <cstdint>

#define S 2048
#define C 4096
#define K 4
#define ND 9            // offsets d=-4..4
#define KKB 36          // K*ND per precision part
#define TM 64           // samples per CTA
#define TN 64           // channels per CTA
#define NKS 7           // k-steps of 16 (K=112 >= 108)
#define QSTR 60         // b32 (k-pair) words per row: conflict-free fragment LDS
#define SMEM_BYTES ((TM + TN) * QSTR * 4)   // 30720

static __device__ __forceinline__ void mma16816(float c[4], const uint32_t a[4],
                                                uint32_t b0, uint32_t b1) {
    asm volatile(
        "mma.sync.aligned.m16n8k16.row.col.f32.bf16.bf16.f32 "
        "{%0,%1,%2,%3}, {%4,%5,%6,%7}, {%8,%9}, {%0,%1,%2,%3};"
        : "+f"(c[0]), "+f"(c[1]), "+f"(c[2]), "+f"(c[3])
        : "r"(a[0]), "r"(a[1]), "r"(a[2]), "r"(a[3]), "r"(b0), "r"(b1));
}

// out(S,C) = A(S,108) * B(108,C); A'=[Ahi|Ahi|Alo], B'=[Bhi;Blo;Bhi].
// A[s][p*36+k*9+r..+1]={w0,w1}; B[p*36+k*9+(d+4)][c]=comp[k][c+d] (0 OOB).
// CTA: 128 threads, tile 64(M) x 64(N); warps 2(M)x2(N), warp tile 32x32.
__global__ void __launch_bounds__(128, 7)
smf_hmma(const float* __restrict__ comp,      // (K, C)
         const float* __restrict__ contrib,   // (S, K)
         const float* __restrict__ shift,     // (S, K)
         float* __restrict__ out)             // (S, C)
{
    extern __shared__ uint32_t sm[];
    uint32_t* sA = sm;                 // [TM][QSTR] b32 k-pairs
    uint32_t* sB = sm + TM * QSTR;     // [TN][QSTR]

    const int tid   = threadIdx.x;
    const int wid   = tid >> 5;
    const int lane  = tid & 31;
    const int g     = lane >> 2;       // groupID (0..7)
    const int tg    = lane & 3;        // thread-in-group
    const int cN0   = blockIdx.x * TN;
    const int s0    = blockIdx.y * TM;
    const int warpM = wid & 1;         // 2 warps along M
    const int warpN = wid >> 1;        // 2 warps along N

    // ---- B build: batch all 18 loads (full MLP), then convert+store ----
    // Thread covers channel row n = tid&63, bands kk = 2*it + (tid>>6).
    {
        const int n  = tid & 63;
        const int hi = tid >> 6;       // 0 or 1
        float v[18];
#pragma unroll
        for (int it = 0; it < 18; it++) {
            const int kk = 2 * it + hi;
            const int k  = kk / ND;
            const int d  = kk - k * ND - 4;
            const int gc = cN0 + n + d;
            v[it] = (gc >= 0 && gc < C) ? __ldg(&comp[k * C + gc]) : 0.f;
        }
        __nv_bfloat16* Bh = reinterpret_cast<__nv_bfloat16*>(sB + n * QSTR);
        if (hi == 0) {                  // zero pad bands 108..111 (own row, pre-sync)
            sB[n * QSTR + 54] = 0u;
            sB[n * QSTR + 55] = 0u;
        }
#pragma unroll
        for (int it = 0; it < 18; it++) {
            const int kk = 2 * it + hi;
            const __nv_bfloat16 vh = __float2bfloat16(v[it]);
            const __nv_bfloat16 vl = __float2bfloat16(v[it] - __bfloat162float(vh));
            Bh[kk]           = vh;      // part 0: hi
            Bh[kk + KKB]     = vl;      // part 1: lo
            Bh[kk + 2 * KKB] = vh;      // part 2: hi
        }
    }

    // ---- A build: thread tid<64 owns sample row tid ----
    if (tid < TM) {
        const float4 sh4 = __ldg(reinterpret_cast<const float4*>(shift + (s0 + tid) * K));
        const float4 w4  = __ldg(reinterpret_cast<const float4*>(contrib + (s0 + tid) * K));
        float4* Az = reinterpret_cast<float4*>(sA + tid * QSTR);   // 240B rows, 16B aligned
#pragma unroll
        for (int i = 0; i < QSTR / 4; i++) Az[i] = make_float4(0.f, 0.f, 0.f, 0.f);

        const float shs[4] = {sh4.x, sh4.y, sh4.z, sh4.w};
        const float ws[4]  = {w4.x,  w4.y,  w4.z,  w4.w};
        __nv_bfloat16* Ah = reinterpret_cast<__nv_bfloat16*>(sA + tid * QSTR);
#pragma unroll
        for (int k = 0; k < K; k++) {
            const float m = floorf(shs[k]);
            const float f = shs[k] - m;
            int r = (int)m + 4;                    // shift in [-4,4) -> r in [0,7]
            r = max(0, min(7, r));
            const float w1 = ws[k] * f;
            const float w0 = ws[k] - w1;
            const __nv_bfloat16 w0h = __float2bfloat16(w0);
            const __nv_bfloat16 w1h = __float2bfloat16(w1);
            const __nv_bfloat16 w0l = __float2bfloat16(w0 - __bfloat162float(w0h));
            const __nv_bfloat16 w1l = __float2bfloat16(w1 - __bfloat162float(w1h));
            const int c0 = k * ND + r;
            Ah[c0]           = w0h;  Ah[c0 + 1]           = w1h;   // hi
            Ah[c0 + KKB]     = w0h;  Ah[c0 + KKB + 1]     = w1h;   // hi (x B lo)
            Ah[c0 + 2*KKB]   = w0l;  Ah[c0 + 2*KKB + 1]   = w1l;   // lo (x B hi)
        }
    }
    __syncthreads();

    // ---- mainloop: 7 ksteps, warp tile 32(M) x 32(N) ----
    float c[2][4][4];
#pragma unroll
    for (int mi = 0; mi < 2; mi++)
#pragma unroll
        for (int nj = 0; nj < 4; nj++)
#pragma unroll
            for (int q = 0; q < 4; q++) c[mi][nj][q] = 0.f;

    const uint32_t* Abase = sA + (warpM * 32 + g) * QSTR + tg;
    const uint32_t* Bbase = sB + (warpN * 32 + g) * QSTR + tg;

#pragma unroll
    for (int ks = 0; ks < NKS; ks++) {
        uint32_t a[2][4];
#pragma unroll
        for (int mi = 0; mi < 2; mi++) {
            const uint32_t* ap = Abase + mi * 16 * QSTR + ks * 8;
            a[mi][0] = ap[0];
            a[mi][1] = ap[8 * QSTR];
            a[mi][2] = ap[4];
            a[mi][3] = ap[8 * QSTR + 4];
        }
#pragma unroll
        for (int nj = 0; nj < 4; nj++) {
            const uint32_t* bp = Bbase + nj * 8 * QSTR + ks * 8;
            const uint32_t b0 = bp[0];
            const uint32_t b1 = bp[4];
#pragma unroll
            for (int mi = 0; mi < 2; mi++)
                mma16816(c[mi][nj], a[mi], b0, b1);
        }
    }

    // ---- epilogue: c0,c1 -> (row, 2 cols), c2,c3 -> (row+8, 2 cols) ----
    {
        const int row0 = s0 + warpM * 32 + g;
        const int col0 = cN0 + warpN * 32 + 2 * tg;
#pragma unroll
        for (int mi = 0; mi < 2; mi++) {
            const int r0 = row0 + 16 * mi;
#pragma unroll
            for (int nj = 0; nj < 4; nj++) {
                const int cc = col0 + 8 * nj;
                *reinterpret_cast<float2*>(out + (size_t)r0 * C + cc) =
                    make_float2(c[mi][nj][0], c[mi][nj][1]);
                *reinterpret_cast<float2*>(out + (size_t)(r0 + 8) * C + cc) =
                    make_float2(c[mi][nj][2], c[mi][nj][3]);
            }
        }
    }
}

extern "C" void kernel_launch(void* const* d_in, const int* in_sizes, int n_in,
                              void* d_out, int out_size) {
    // metadata order: inputs (unused), components, contributions, shift
    const float* comp    = (const float*)d_in[1];
    const float* contrib = (const float*)d_in[2];
    const float* shift   = (const float*)d_in[3];
    float*       out     = (float*)d_out;

    static bool configured = false;
    if (!configured) {
        cudaFuncSetAttribute(smf_hmma,
                             cudaFuncAttributeMaxDynamicSharedMemorySize, SMEM_BYTES);
        configured = true;
    }

    dim3 grid(C / TN, S / TM);   // (64, 32) = 2048 CTAs
    smf_hmma<<<grid, 128, SMEM_BYTES>>>(comp, contrib, shift, out);
}

// round 16
// speedup vs baseline: 3.3794x; 1.3439x over previous
#include <cuda_runtime.h>

#define S 2048
#define C 4096
#define K 4
#define SCHUNK 8            // samples per block
#define BLKCH 1024          // channels per block (256 thr * 4 ch)

// Per-sample params, block-shared (tiny: 384 B).
struct Params {
    float4 w0[SCHUNK];      // tap0 weight per k
    float4 w1[SCHUNK];      // tap1 weight per k
    int4   r [SCHUNK];      // tap offset r = mi+4 in [0,7], per k
};

// Branchless tap select + accumulate: x[j] = w[r+j] via 3-level FSEL tree
// (r = 4*b2 + 2*b1 + b0), then 8 FFMA. No BSSY/BSYNC, no memory.
__device__ __forceinline__ void tap_sel(const float (&w)[12], int r, float W0, float W1,
                                        float& a0, float& a1, float& a2, float& a3) {
    const bool b2 = (r & 4) != 0;
    const bool b1 = (r & 2) != 0;
    const bool b0 = (r & 1) != 0;
    float z[8];
#pragma unroll
    for (int i = 0; i < 8; i++) z[i] = b2 ? w[i + 4] : w[i];
    float y[6];
#pragma unroll
    for (int i = 0; i < 6; i++) y[i] = b1 ? z[i + 2] : z[i];
    float x[5];
#pragma unroll
    for (int i = 0; i < 5; i++) x[i] = b0 ? y[i + 1] : y[i];
    a0 = fmaf(W0, x[0], fmaf(W1, x[1], a0));
    a1 = fmaf(W0, x[1], fmaf(W1, x[2], a1));
    a2 = fmaf(W0, x[2], fmaf(W1, x[3], a2));
    a3 = fmaf(W0, x[3], fmaf(W1, x[4], a3));
}

// Thread owns 4 consecutive channels; its 12-word window per component
// (comp[k][c-4 .. c+7], zero-padded at row edges) lives in REGISTERS.
// Per (sample,k): 19 FSEL + 8 FFMA, zero tap loads, zero branches.
__global__ void __launch_bounds__(256, 3)
smf_kernel(const float* __restrict__ comp,      // (K, C)
           const float* __restrict__ contrib,   // (S, K)
           const float* __restrict__ shift,     // (S, K)
           float* __restrict__ out)             // (S, C)
{
    __shared__ Params p;

    const int tid = threadIdx.x;
    const int B0  = blockIdx.x * BLKCH;
    const int s0  = blockIdx.y * SCHUNK;

    // ---- params: thread t<32 handles (sample t>>2, comp t&3) ----
    if (tid < SCHUNK * K) {
        const int sl = tid >> 2;
        const int kk = tid & 3;
        const float sh = __ldg(&shift[(s0 + sl) * K + kk]);
        const float wc = __ldg(&contrib[(s0 + sl) * K + kk]);
        const float m  = floorf(sh);
        const float f  = sh - m;
        int r = (int)m + 4;                      // shift in [-4,4) -> r in [0,7]
        r = max(0, min(7, r));
        const float w1 = wc * f;
        reinterpret_cast<float*>(&p.w0[sl])[kk] = wc - w1;
        reinterpret_cast<float*>(&p.w1[sl])[kk] = w1;
        reinterpret_cast<int*>(&p.r[sl])[kk]    = r;
    }

    // ---- register window: 3 aligned LDG.128 per component (L1-resident) ----
    const int c  = B0 + 4 * tid;                 // thread's first channel
    const int i4 = c >> 2;
    float w[K][12];
#pragma unroll
    for (int k = 0; k < K; k++) {
        const float4* c4 = reinterpret_cast<const float4*>(comp + k * C);
        const float4 z4 = make_float4(0.f, 0.f, 0.f, 0.f);
        const float4 va = (i4 > 0)         ? __ldg(&c4[i4 - 1]) : z4;
        const float4 vb = __ldg(&c4[i4]);
        const float4 vc = (i4 < C / 4 - 1) ? __ldg(&c4[i4 + 1]) : z4;
        w[k][0] = va.x; w[k][1]  = va.y; w[k][2]  = va.z; w[k][3]  = va.w;
        w[k][4] = vb.x; w[k][5]  = vb.y; w[k][6]  = vb.z; w[k][7]  = vb.w;
        w[k][8] = vc.x; w[k][9]  = vc.y; w[k][10] = vc.z; w[k][11] = vc.w;
    }
    __syncthreads();

    float* op = out + (size_t)s0 * C + c;

#pragma unroll 1
    for (int sl = 0; sl < SCHUNK; sl++) {
        const float4 W0 = p.w0[sl];              // broadcast LDS.128
        const float4 W1 = p.w1[sl];
        const int4   R  = p.r[sl];

        float a0 = 0.f, a1 = 0.f, a2 = 0.f, a3 = 0.f;
        tap_sel(w[0], R.x, W0.x, W1.x, a0, a1, a2, a3);
        tap_sel(w[1], R.y, W0.y, W1.y, a0, a1, a2, a3);
        tap_sel(w[2], R.z, W0.z, W1.z, a0, a1, a2, a3);
        tap_sel(w[3], R.w, W0.w, W1.w, a0, a1, a2, a3);

        *reinterpret_cast<float4*>(op) = make_float4(a0, a1, a2, a3);
        op += C;
    }
}

extern "C" void kernel_launch(void* const* d_in, const int* in_sizes, int n_in,
                              void* d_out, int out_size) {
    // metadata order: inputs (unused), components, contributions, shift
    const float* comp    = (const float*)d_in[1];
    const float* contrib = (const float*)d_in[2];
    const float* shift   = (const float*)d_in[3];
    float*       out     = (float*)d_out;

    dim3 grid(C / BLKCH, S / SCHUNK);   // (4, 256) = 1024 blocks
    smf_kernel<<<grid, 256>>>(comp, contrib, shift, out);
}